// round 16
// baseline (speedup 1.0000x reference)
#include <cuda_runtime.h>
#include <cuda_fp16.h>
#include <math.h>
#include <stdint.h>

// Problem dims (fixed)
#define BWN 4096   // B*W
#define HD  512    // hidden
#define QD  256    // quantized repr
#define AD  128    // alphabet
#define CD  16     // chars per word
#define G4H 2048   // 4*H

// ============================================================================
// PTX helpers
// ============================================================================
__device__ __forceinline__ uint32_t smem_u32(const void* p) {
    uint32_t a;
    asm("{ .reg .u64 t; cvta.to.shared.u64 t, %1; cvt.u32.u64 %0, t; }"
        : "=r"(a) : "l"(p));
    return a;
}
__device__ __forceinline__ void mma16816(float (&d)[4], const uint32_t (&a)[4],
                                         const uint32_t (&b)[2]) {
    asm volatile("mma.sync.aligned.m16n8k16.row.col.f32.f16.f16.f32 "
                 "{%0,%1,%2,%3}, {%4,%5,%6,%7}, {%8,%9}, {%0,%1,%2,%3};"
                 : "+f"(d[0]), "+f"(d[1]), "+f"(d[2]), "+f"(d[3])
                 : "r"(a[0]), "r"(a[1]), "r"(a[2]), "r"(a[3]),
                   "r"(b[0]), "r"(b[1]));
}
__device__ __forceinline__ void cp_async16(uint32_t saddr, const void* g) {
    asm volatile("cp.async.cg.shared.global [%0], [%1], 16;"
                 :: "r"(saddr), "l"(g) : "memory");
}
#define CP_COMMIT() asm volatile("cp.async.commit_group;" ::: "memory")
#define CP_WAIT0()  asm volatile("cp.async.wait_group 0;" ::: "memory")

// ============================================================================
// Device state (no allocation allowed)
// h buffers hold A-FRAGMENT layout: tile (mt=m>>4, kt=k>>4);
//   halves index = ((mt*32 + kt)*32 + lane)*8 + reg*2 + half
// ============================================================================
__device__ __half g_h0[BWN * HD];
__device__ __half g_h1[BWN * HD];
__device__ float  g_c[BWN * HD];                     // MMA-fragment layout
__device__ __half g_WB[G4H * HD];                    // W_hh in B-fragment order
__device__ __half g_WoB[AD * HD];                    // Wo in B-fragment order
__device__ float  g_xbT[AD * G4H];                   // fragment-ordered xbias
__device__ __half g_XA[BWN * QD];                    // X in A-fragment order (fp16)
__device__ __half g_WpHi[HD * QD], g_WpLo[HD * QD];  // Wp B-fragments, fp16 split

__device__ __forceinline__ float sigmoidf_(float x) {
    return __fdividef(1.0f, 1.0f + __expf(-x));
}
__device__ __forceinline__ float tanhf_(float x) {
    return 1.0f - __fdividef(2.0f, __expf(2.0f * x) + 1.0f);
}
__device__ __forceinline__ void f16_split(float v, __half& hi, __half& lo) {
    hi = __float2half_rn(v);
    lo = __float2half_rn(v - __half2float(hi));
}

// ============================================================================
// prep_all — one launch, 9984 blocks (layouts validated R9-R15).
// ============================================================================
__global__ void prep_all(const float* __restrict__ Whh,
                         const float* __restrict__ X,
                         const float* __restrict__ Wih,
                         const float* __restrict__ bih,
                         const float* __restrict__ bhh,
                         const float* __restrict__ Wo,
                         const float* __restrict__ Wp,
                         __half* __restrict__ WB,
                         __half* __restrict__ XA,
                         float* __restrict__ xb,
                         __half* __restrict__ WoB,
                         __half* __restrict__ WpHi,
                         __half* __restrict__ WpLo)
{
    const int b = blockIdx.x;
    if (b < 4096) {                                  // WB
        int i = b * 256 + threadIdx.x;               // over 2048*512
        int lane = (i >> 3) & 31, j = i & 7;
        int block = i >> 8;
        int fpair = block & 1, wn = (block >> 1) & 3, ks = (block >> 3) & 3;
        int kc = (block >> 5) & 7, bn = block >> 8;
        int f = fpair * 2 + (j >> 2);
        int reg = (j >> 1) & 1, h = j & 1;
        int n = f * HD + bn * 32 + wn * 8 + (lane >> 2);
        int k = kc * 64 + ks * 16 + (lane & 3) * 2 + reg * 8 + h;
        WB[i] = __float2half_rn(Whh[n * HD + k]);
    } else if (b < 8192) {                           // XA
        int i = (b - 4096) * 256 + threadIdx.x;      // over 4096*256
        int jj = i & 7, lane = (i >> 3) & 31, kt = (i >> 8) & 15, mt = i >> 12;
        int m = mt * 16 + (lane >> 2) + ((jj >> 1) & 1) * 8;
        int k = kt * 16 + (lane & 3) * 2 + ((jj >> 2) & 1) * 8 + (jj & 1);
        XA[i] = __float2half_rn(X[m * QD + k]);
    } else if (b < 9216) {                           // xbias
        int q = (b - 8192) * 256 + threadIdx.x;      // over 128*2048
        int a = q >> 11, bn = (q >> 7) & 15, wn = (q >> 5) & 3, jl = (q >> 2) & 7, g = q & 3;
        int n = g * HD + bn * 32 + wn * 8 + jl;
        xb[q] = Wih[n * AD + a] + bih[n] + bhh[n];
    } else if (b < 9472) {                           // WoB
        int i = (b - 9216) * 256 + threadIdx.x;      // over 128*512
        int j = i & 7, lane = (i >> 3) & 31, wid = (i >> 8) & 7, kt = i >> 11;
        int n = wid * 16 + (j >> 2) * 8 + (lane >> 2);
        int k = kt * 16 + (lane & 3) * 2 + ((j >> 1) & 1) * 8 + (j & 1);
        WoB[i] = __float2half_rn(Wo[n * HD + k]);
    } else {                                         // WpB hi/lo
        int i = (b - 9472) * 256 + threadIdx.x;      // over 512*256
        int j = i & 7, lane = (i >> 3) & 31, wid = (i >> 8) & 7;
        int kt = (i >> 11) & 15, nb = i >> 15;
        int n = nb * 128 + wid * 16 + (j >> 2) * 8 + (lane >> 2);
        int k = kt * 16 + (lane & 3) * 2 + ((j >> 1) & 1) * 8 + (j & 1);
        __half hi, lo; f16_split(Wp[n * QD + k], hi, lo);
        WpHi[i] = hi; WpLo[i] = lo;
    }
}

// ============================================================================
// h0 via HMMA: h0 = X @ Wp^T + bp  (M=4096, N=512, K=256).
// ============================================================================
__global__ __launch_bounds__(256, 2) void h0_hmma(
    const __half* __restrict__ XA,
    const __half* __restrict__ WpHi,
    const __half* __restrict__ WpLo,
    const float* __restrict__ bp,
    __half* __restrict__ hout)
{
    const int tid = threadIdx.x;
    const int wid = tid >> 5, lane = tid & 31;
    const int bx = blockIdx.x;        // m tile: m0 = bx*32
    const int nb = blockIdx.y;        // n block of 128

    const __half* aP = XA + (bx * 2) * 4096 + lane * 8;
    const __half* bH = WpHi + ((nb * 16) * 8 + wid) * 256 + lane * 8;
    const __half* bL = WpLo + ((nb * 16) * 8 + wid) * 256 + lane * 8;

    float acc[2][2][4];
    #pragma unroll
    for (int a = 0; a < 2; a++)
        #pragma unroll
        for (int c = 0; c < 2; c++)
            #pragma unroll
            for (int d = 0; d < 4; d++) acc[a][c][d] = 0.0f;

    #pragma unroll
    for (int kt = 0; kt < 16; kt++) {
        const uint4 aq0 = *(const uint4*)(aP + kt * 256);
        const uint4 aq1 = *(const uint4*)(aP + 4096 + kt * 256);
        const uint4 qh  = *(const uint4*)(bH + kt * 2048);
        const uint4 ql  = *(const uint4*)(bL + kt * 2048);
        uint32_t af0[4] = {aq0.x, aq0.y, aq0.z, aq0.w};
        uint32_t af1[4] = {aq1.x, aq1.y, aq1.z, aq1.w};
        uint32_t bh[2][2], bl[2][2];
        bh[0][0] = qh.x; bh[0][1] = qh.y; bh[1][0] = qh.z; bh[1][1] = qh.w;
        bl[0][0] = ql.x; bl[0][1] = ql.y; bl[1][0] = ql.z; bl[1][1] = ql.w;
        #pragma unroll
        for (int f = 0; f < 2; f++) {
            mma16816(acc[0][f], af0, bh[f]);
            mma16816(acc[1][f], af1, bh[f]);
            mma16816(acc[0][f], af0, bl[f]);
            mma16816(acc[1][f], af1, bl[f]);
        }
    }

    const int lr = lane >> 2;
    const int lc = (lane & 3) * 2;
    const int ktj = nb * 8 + wid;
    #pragma unroll
    for (int mi = 0; mi < 2; mi++) {
        const int mt = bx * 2 + mi;
        __half* base = hout + (mt * 32 + ktj) * 256 + (lr * 4 + (lc >> 1)) * 8;
        #pragma unroll
        for (int f = 0; f < 2; f++) {
            const int n = nb * 128 + wid * 16 + f * 8 + lc;
            const float2 b2 = *(const float2*)(bp + n);
            const __half h00 = __float2half_rn(acc[mi][f][0] + b2.x);
            const __half h01 = __float2half_rn(acc[mi][f][1] + b2.y);
            const __half h10 = __float2half_rn(acc[mi][f][2] + b2.x);
            const __half h11 = __float2half_rn(acc[mi][f][3] + b2.y);
            uint2 w;
            w.x = (uint32_t)__half_as_ushort(h00) | ((uint32_t)__half_as_ushort(h01) << 16);
            w.y = (uint32_t)__half_as_ushort(h10) | ((uint32_t)__half_as_ushort(h11) << 16);
            *(uint2*)(base + 4 * f) = w;
        }
    }
}

// ============================================================================
// Merged step kernel — R15 champion with WAVE-PACKING REORDER:
//   blocks [0,128)   : logits(t-1)  (LIGHT — launched first so they occupy
//                      wave-1 slots and free them early; tail is uniform gates)
//   blocks [128,640) : gates(t)
// ============================================================================
#define A_SMEM_BYTES 65536      // 64 rows x 512 k x 2B, fragment layout

__global__ __launch_bounds__(256, 2) void step_kernel(
    int t,
    const __half* __restrict__ hin,
    __half*       __restrict__ hout,
    const __half* __restrict__ WB,
    const float* __restrict__ xbT,
    const int* __restrict__ chars,
    float* __restrict__ cst,
    const __half* __restrict__ WoB,
    const float* __restrict__ bo,
    float* __restrict__ out)
{
    extern __shared__ __half sA[];
    const int tid = threadIdx.x;
    const int wid = tid >> 5, lane = tid & 31;
    const int bx = blockIdx.x;

    if (bx >= 128) {
        // ======================= GATES PATH =======================
        const int bxg = bx - 128;
        const int bm = bxg & 63, bnp = bxg >> 6;    // 64 x 8
        const int m0 = bm * 64;
        const int bn0 = bnp * 2, bn1 = bn0 + 1;
        const int wm = wid >> 2, wn = wid & 3;      // 2m x 4n warps
        const int lr = lane >> 2;
        const int lc = (lane & 3) * 2;

        // Stage full A tile to smem (fragment-contiguous range).
        {
            const uint32_t sbase = smem_u32(sA);
            const __half* aG = hin + (bm * 4 * 32) * 256;
            #pragma unroll
            for (int i = 0; i < 16; i++) {
                const int ch = tid + i * 256;          // 0..4095 16B-chunks
                cp_async16(sbase + ch * 16, aG + ch * 8);
            }
            CP_COMMIT();
        }

        // Hoisted: char indices for epilogue (overlaps with GEMM).
        int cidx[2][2];
        #pragma unroll
        for (int mi = 0; mi < 2; mi++)
            #pragma unroll
            for (int rh = 0; rh < 2; rh++) {
                const int m = m0 + wm*32 + mi*16 + lr + rh*8;
                int idx = 0;
                if (t > 0) {
                    int cc = chars[m * CD + (t - 1)];
                    idx = (cc >= 0 && cc < AD) ? cc : 0;
                }
                cidx[mi][rh] = idx;
            }

        // B fragment bases for the two bn blocks (kt stride 2048)
        const __half* bP0 = WB + (bn0 * 256 + wn * 2) * 256 + lane * 8;
        const __half* bP1 = WB + (bn1 * 256 + wn * 2) * 256 + lane * 8;

        // Prefetch B stage 0 while A streams in
        uint4 Ba[2][2], Bb[2][2];
        Ba[0][0] = *(const uint4*)(bP0);
        Ba[1][0] = *(const uint4*)(bP0 + 256);
        Bb[0][0] = *(const uint4*)(bP1);
        Bb[1][0] = *(const uint4*)(bP1 + 256);

        float acc[2][2][4][4];   // [mi][blk][f][k]
        #pragma unroll
        for (int a = 0; a < 2; a++)
            #pragma unroll
            for (int b = 0; b < 2; b++)
                #pragma unroll
                for (int c = 0; c < 4; c++)
                    #pragma unroll
                    for (int d = 0; d < 4; d++) acc[a][b][c][d] = 0.0f;

        CP_WAIT0();
        __syncthreads();

        const __half* aS0 = sA + (wm * 2) * 8192 + lane * 8;       // mi=0
        const __half* aS1 = aS0 + 8192;                            // mi=1

        #pragma unroll
        for (int kt = 0; kt < 32; kt++) {
            const int cur = kt & 1, nxt = cur ^ 1;
            if (kt < 31) {
                const int kb = (kt + 1) * 2048;
                Ba[0][nxt] = *(const uint4*)(bP0 + kb);
                Ba[1][nxt] = *(const uint4*)(bP0 + kb + 256);
                Bb[0][nxt] = *(const uint4*)(bP1 + kb);
                Bb[1][nxt] = *(const uint4*)(bP1 + kb + 256);
            }
            const uint4 aq0 = *(const uint4*)(aS0 + kt * 256);     // LDS.128
            const uint4 aq1 = *(const uint4*)(aS1 + kt * 256);
            uint32_t af0[4] = {aq0.x, aq0.y, aq0.z, aq0.w};
            uint32_t af1[4] = {aq1.x, aq1.y, aq1.z, aq1.w};
            uint32_t bf0[4][2], bf1[4][2];
            bf0[0][0] = Ba[0][cur].x; bf0[0][1] = Ba[0][cur].y;
            bf0[1][0] = Ba[0][cur].z; bf0[1][1] = Ba[0][cur].w;
            bf0[2][0] = Ba[1][cur].x; bf0[2][1] = Ba[1][cur].y;
            bf0[3][0] = Ba[1][cur].z; bf0[3][1] = Ba[1][cur].w;
            bf1[0][0] = Bb[0][cur].x; bf1[0][1] = Bb[0][cur].y;
            bf1[1][0] = Bb[0][cur].z; bf1[1][1] = Bb[0][cur].w;
            bf1[2][0] = Bb[1][cur].x; bf1[2][1] = Bb[1][cur].y;
            bf1[3][0] = Bb[1][cur].z; bf1[3][1] = Bb[1][cur].w;
            #pragma unroll
            for (int f = 0; f < 4; f++) {
                mma16816(acc[0][0][f], af0, bf0[f]);
                mma16816(acc[1][0][f], af1, bf0[f]);
                mma16816(acc[0][1][f], af0, bf1[f]);
                mma16816(acc[1][1][f], af1, bf1[f]);
            }
        }

        // Epilogue: per bn block, gates -> LSTM cell update.
        #pragma unroll
        for (int blk = 0; blk < 2; blk++) {
            const int bn = bn0 + blk;
            float* cp_base = cst + (((bm * 16 + bn) * 8 + wid) * 256 + lane * 8);
            #pragma unroll
            for (int mi = 0; mi < 2; mi++) {
                float4 cold = (t > 0) ? *(float4*)(cp_base + mi * 4)
                                      : make_float4(0.f, 0.f, 0.f, 0.f);
                float cn_[4];
                uint32_t ph[2];
                #pragma unroll
                for (int rh = 0; rh < 2; rh++) {
                    const float* xb = xbT + ((cidx[mi][rh] * 16 + bn) * 4 + wn) * 32 + lc * 4;
                    const float4 x0 = *(const float4*)xb;
                    const float4 x1 = *(const float4*)(xb + 4);
                    __half hv[2];
                    #pragma unroll
                    for (int cpp = 0; cpp < 2; cpp++) {
                        const float4 xv = cpp ? x1 : x0;
                        const int k = rh * 2 + cpp;
                        const float gi = acc[mi][blk][0][k] + xv.x;
                        const float gf = acc[mi][blk][1][k] + xv.y;
                        const float gg = acc[mi][blk][2][k] + xv.z;
                        const float go = acc[mi][blk][3][k] + xv.w;
                        const float co = (k == 0) ? cold.x : (k == 1) ? cold.y
                                       : (k == 2) ? cold.z : cold.w;
                        const float cn = sigmoidf_(gf) * co + sigmoidf_(gi) * tanhf_(gg);
                        cn_[k] = cn;
                        hv[cpp] = __float2half_rn(sigmoidf_(go) * tanhf_(cn));
                    }
                    ph[rh] = (uint32_t)__half_as_ushort(hv[0])
                           | ((uint32_t)__half_as_ushort(hv[1]) << 16);
                }
                const int mt = bm*4 + wm*2 + mi;
                const int ktj = bn*2 + (wn >> 1);
                uint2 w; w.x = ph[0]; w.y = ph[1];
                *(uint2*)(hout + (mt*32 + ktj)*256 + lane*8 + (wn & 1)*4) = w;
                *(float4*)(cp_base + mi * 4) = make_float4(cn_[0], cn_[1], cn_[2], cn_[3]);
            }
        }
    } else {
        // ============== LOGITS PATH (for step t-1) — runs FIRST ==============
        if (t == 0) return;
        const int m0 = bx * 32;
        const int tprev = t - 1;

        const __half* aP = hin + ((m0 >> 4) * 32) * 256 + lane * 8;
        const __half* bP = WoB + (wid * 32 + lane) * 8;

        float acc[2][2][4];
        #pragma unroll
        for (int a = 0; a < 2; a++)
            #pragma unroll
            for (int b = 0; b < 2; b++)
                #pragma unroll
                for (int c = 0; c < 4; c++) acc[a][b][c] = 0.0f;

        #pragma unroll
        for (int kt = 0; kt < 32; kt++) {
            const uint4 aq0 = *(const uint4*)(aP + kt * 256);
            const uint4 aq1 = *(const uint4*)(aP + 8192 + kt * 256);
            const uint4 bq  = *(const uint4*)(bP + kt * 2048);
            uint32_t af0[4] = {aq0.x, aq0.y, aq0.z, aq0.w};
            uint32_t af1[4] = {aq1.x, aq1.y, aq1.z, aq1.w};
            uint32_t bf[2][2];
            bf[0][0] = bq.x; bf[0][1] = bq.y;
            bf[1][0] = bq.z; bf[1][1] = bq.w;
            mma16816(acc[0][0], af0, bf[0]);
            mma16816(acc[0][1], af0, bf[1]);
            mma16816(acc[1][0], af1, bf[0]);
            mma16816(acc[1][1], af1, bf[1]);
        }

        const int lr = lane >> 2;
        const int lc = (lane & 3) * 2;
        #pragma unroll
        for (int mi = 0; mi < 2; mi++) {
            #pragma unroll
            for (int rh = 0; rh < 2; rh++) {
                const int m = m0 + mi*16 + lr + rh*8;
                float* orow = out + m * (CD * AD) + tprev * AD;
                #pragma unroll
                for (int f = 0; f < 2; f++) {
                    const int n = wid*16 + f*8 + lc;
                    const float2 b2 = *(const float2*)(bo + n);
                    float2 v;
                    v.x = acc[mi][f][rh*2 + 0] + b2.x;
                    v.y = acc[mi][f][rh*2 + 1] + b2.y;
                    *(float2*)(orow + n) = v;
                }
            }
        }
    }
}

// ============================================================================
// Standalone logits (final step).
// ============================================================================
__global__ __launch_bounds__(256, 2) void logits_kernel(
    const __half* __restrict__ h,
    const __half* __restrict__ WoB,
    const float* __restrict__ bo,
    float* __restrict__ out, int t)
{
    const int tid = threadIdx.x;
    const int wid = tid >> 5, lane = tid & 31;
    const int m0 = blockIdx.x * 32;

    const __half* aP = h + ((m0 >> 4) * 32) * 256 + lane * 8;
    const __half* bP = WoB + (wid * 32 + lane) * 8;

    float acc[2][2][4];
    #pragma unroll
    for (int a = 0; a < 2; a++)
        #pragma unroll
        for (int b = 0; b < 2; b++)
            #pragma unroll
            for (int c = 0; c < 4; c++) acc[a][b][c] = 0.0f;

    #pragma unroll
    for (int kt = 0; kt < 32; kt++) {
        const uint4 aq0 = *(const uint4*)(aP + kt * 256);
        const uint4 aq1 = *(const uint4*)(aP + 8192 + kt * 256);
        const uint4 bq  = *(const uint4*)(bP + kt * 2048);
        uint32_t af0[4] = {aq0.x, aq0.y, aq0.z, aq0.w};
        uint32_t af1[4] = {aq1.x, aq1.y, aq1.z, aq1.w};
        uint32_t bf[2][2];
        bf[0][0] = bq.x; bf[0][1] = bq.y;
        bf[1][0] = bq.z; bf[1][1] = bq.w;
        mma16816(acc[0][0], af0, bf[0]);
        mma16816(acc[0][1], af0, bf[1]);
        mma16816(acc[1][0], af1, bf[0]);
        mma16816(acc[1][1], af1, bf[1]);
    }

    const int lr = lane >> 2;
    const int lc = (lane & 3) * 2;
    #pragma unroll
    for (int mi = 0; mi < 2; mi++) {
        #pragma unroll
        for (int rh = 0; rh < 2; rh++) {
            const int m = m0 + mi*16 + lr + rh*8;
            float* orow = out + m * (CD * AD) + t * AD;
            #pragma unroll
            for (int f = 0; f < 2; f++) {
                const int n = wid*16 + f*8 + lc;
                const float2 b2 = *(const float2*)(bo + n);
                float2 v;
                v.x = acc[mi][f][rh*2 + 0] + b2.x;
                v.y = acc[mi][f][rh*2 + 1] + b2.y;
                *(float2*)(orow + n) = v;
            }
        }
    }
}

// ============================================================================
// kernel_launch
// ============================================================================
extern "C" void kernel_launch(void* const* d_in, const int* in_sizes, int n_in,
                              void* d_out, int out_size)
{
    const float* X    = (const float*)d_in[0];
    const int*   tc   = (const int*)  d_in[1];
    const float* Wp   = (const float*)d_in[2];
    const float* bp   = (const float*)d_in[3];
    const float* Wih  = (const float*)d_in[4];
    const float* Whh  = (const float*)d_in[5];
    const float* bih  = (const float*)d_in[6];
    const float* bhh  = (const float*)d_in[7];
    const float* Wo   = (const float*)d_in[8];
    const float* bo   = (const float*)d_in[9];
    float* out = (float*)d_out;

    __half *h0b, *h1b, *wb, *wob, *xa, *wphi, *wplo;
    float *cS, *xb;
    cudaGetSymbolAddress((void**)&h0b,  g_h0);
    cudaGetSymbolAddress((void**)&h1b,  g_h1);
    cudaGetSymbolAddress((void**)&cS,   g_c);
    cudaGetSymbolAddress((void**)&wb,   g_WB);
    cudaGetSymbolAddress((void**)&wob,  g_WoB);
    cudaGetSymbolAddress((void**)&xb,   g_xbT);
    cudaGetSymbolAddress((void**)&xa,   g_XA);
    cudaGetSymbolAddress((void**)&wphi, g_WpHi);
    cudaGetSymbolAddress((void**)&wplo, g_WpLo);

    cudaFuncSetAttribute(step_kernel, cudaFuncAttributeMaxDynamicSharedMemorySize,
                         A_SMEM_BYTES);

    prep_all<<<9984, 256>>>(Whh, X, Wih, bih, bhh, Wo, Wp,
                            wb, xa, xb, wob, wphi, wplo);
    h0_hmma<<<dim3(128, 4), 256>>>(xa, wphi, wplo, bp, h0b);

    for (int t = 0; t < CD; t++) {
        const __half* hin  = (t & 1) ? h1b : h0b;
        __half*       hout = (t & 1) ? h0b : h1b;
        step_kernel<<<640, 256, A_SMEM_BYTES>>>(
            t, hin, hout, wb, xb, tc, cS, wob, bo, out);
    }
    // final logits for t = 15
    logits_kernel<<<BWN / 32, 256>>>(
        (CD & 1) ? h1b : h0b, wob, bo, out, CD - 1);
}

// round 17
// speedup vs baseline: 1.0774x; 1.0774x over previous
#include <cuda_runtime.h>
#include <cuda_fp16.h>
#include <math.h>
#include <stdint.h>

// Problem dims (fixed)
#define BWN 4096   // B*W
#define HD  512    // hidden
#define QD  256    // quantized repr
#define AD  128    // alphabet
#define CD  16     // chars per word
#define G4H 2048   // 4*H

// ============================================================================
// PTX helpers
// ============================================================================
__device__ __forceinline__ uint32_t smem_u32(const void* p) {
    uint32_t a;
    asm("{ .reg .u64 t; cvta.to.shared.u64 t, %1; cvt.u32.u64 %0, t; }"
        : "=r"(a) : "l"(p));
    return a;
}
__device__ __forceinline__ void mma16816(float (&d)[4], const uint32_t (&a)[4],
                                         const uint32_t (&b)[2]) {
    asm volatile("mma.sync.aligned.m16n8k16.row.col.f32.f16.f16.f32 "
                 "{%0,%1,%2,%3}, {%4,%5,%6,%7}, {%8,%9}, {%0,%1,%2,%3};"
                 : "+f"(d[0]), "+f"(d[1]), "+f"(d[2]), "+f"(d[3])
                 : "r"(a[0]), "r"(a[1]), "r"(a[2]), "r"(a[3]),
                   "r"(b[0]), "r"(b[1]));
}
__device__ __forceinline__ void cp_async16(uint32_t saddr, const void* g) {
    asm volatile("cp.async.cg.shared.global [%0], [%1], 16;"
                 :: "r"(saddr), "l"(g) : "memory");
}
__device__ __forceinline__ void stg_cs_f2(float* p, float2 v) {
    asm volatile("st.global.cs.v2.f32 [%0], {%1, %2};"
                 :: "l"(p), "f"(v.x), "f"(v.y) : "memory");
}
#define CP_COMMIT() asm volatile("cp.async.commit_group;" ::: "memory")
#define CP_WAIT0()  asm volatile("cp.async.wait_group 0;" ::: "memory")

// ============================================================================
// Device state (no allocation allowed)
// h buffers hold A-FRAGMENT layout: tile (mt=m>>4, kt=k>>4);
//   halves index = ((mt*32 + kt)*32 + lane)*8 + reg*2 + half
// ============================================================================
__device__ __half g_h0[BWN * HD];
__device__ __half g_h1[BWN * HD];
__device__ float  g_c[BWN * HD];                     // MMA-fragment layout
__device__ __half g_WB[G4H * HD];                    // W_hh in B-fragment order
__device__ __half g_WoB[AD * HD];                    // Wo in B-fragment order
__device__ float  g_xbT[AD * G4H];                   // fragment-ordered xbias
__device__ __half g_XA[BWN * QD];                    // X in A-fragment order (fp16)
__device__ __half g_WpHi[HD * QD], g_WpLo[HD * QD];  // Wp B-fragments, fp16 split

__device__ __forceinline__ float sigmoidf_(float x) {
    return __fdividef(1.0f, 1.0f + __expf(-x));
}
__device__ __forceinline__ float tanhf_(float x) {
    return 1.0f - __fdividef(2.0f, __expf(2.0f * x) + 1.0f);
}
__device__ __forceinline__ void f16_split(float v, __half& hi, __half& lo) {
    hi = __float2half_rn(v);
    lo = __float2half_rn(v - __half2float(hi));
}

// ============================================================================
// prep_all — one launch, 9984 blocks (layouts validated R9-R15).
// ============================================================================
__global__ void prep_all(const float* __restrict__ Whh,
                         const float* __restrict__ X,
                         const float* __restrict__ Wih,
                         const float* __restrict__ bih,
                         const float* __restrict__ bhh,
                         const float* __restrict__ Wo,
                         const float* __restrict__ Wp,
                         __half* __restrict__ WB,
                         __half* __restrict__ XA,
                         float* __restrict__ xb,
                         __half* __restrict__ WoB,
                         __half* __restrict__ WpHi,
                         __half* __restrict__ WpLo)
{
    const int b = blockIdx.x;
    if (b < 4096) {                                  // WB
        int i = b * 256 + threadIdx.x;               // over 2048*512
        int lane = (i >> 3) & 31, j = i & 7;
        int block = i >> 8;
        int fpair = block & 1, wn = (block >> 1) & 3, ks = (block >> 3) & 3;
        int kc = (block >> 5) & 7, bn = block >> 8;
        int f = fpair * 2 + (j >> 2);
        int reg = (j >> 1) & 1, h = j & 1;
        int n = f * HD + bn * 32 + wn * 8 + (lane >> 2);
        int k = kc * 64 + ks * 16 + (lane & 3) * 2 + reg * 8 + h;
        WB[i] = __float2half_rn(Whh[n * HD + k]);
    } else if (b < 8192) {                           // XA
        int i = (b - 4096) * 256 + threadIdx.x;      // over 4096*256
        int jj = i & 7, lane = (i >> 3) & 31, kt = (i >> 8) & 15, mt = i >> 12;
        int m = mt * 16 + (lane >> 2) + ((jj >> 1) & 1) * 8;
        int k = kt * 16 + (lane & 3) * 2 + ((jj >> 2) & 1) * 8 + (jj & 1);
        XA[i] = __float2half_rn(X[m * QD + k]);
    } else if (b < 9216) {                           // xbias
        int q = (b - 8192) * 256 + threadIdx.x;      // over 128*2048
        int a = q >> 11, bn = (q >> 7) & 15, wn = (q >> 5) & 3, jl = (q >> 2) & 7, g = q & 3;
        int n = g * HD + bn * 32 + wn * 8 + jl;
        xb[q] = Wih[n * AD + a] + bih[n] + bhh[n];
    } else if (b < 9472) {                           // WoB
        int i = (b - 9216) * 256 + threadIdx.x;      // over 128*512
        int j = i & 7, lane = (i >> 3) & 31, wid = (i >> 8) & 7, kt = i >> 11;
        int n = wid * 16 + (j >> 2) * 8 + (lane >> 2);
        int k = kt * 16 + (lane & 3) * 2 + ((j >> 1) & 1) * 8 + (j & 1);
        WoB[i] = __float2half_rn(Wo[n * HD + k]);
    } else {                                         // WpB hi/lo
        int i = (b - 9472) * 256 + threadIdx.x;      // over 512*256
        int j = i & 7, lane = (i >> 3) & 31, wid = (i >> 8) & 7;
        int kt = (i >> 11) & 15, nb = i >> 15;
        int n = nb * 128 + wid * 16 + (j >> 2) * 8 + (lane >> 2);
        int k = kt * 16 + (lane & 3) * 2 + ((j >> 1) & 1) * 8 + (j & 1);
        __half hi, lo; f16_split(Wp[n * QD + k], hi, lo);
        WpHi[i] = hi; WpLo[i] = lo;
    }
}

// ============================================================================
// h0 via HMMA: h0 = X @ Wp^T + bp  (M=4096, N=512, K=256).
// ============================================================================
__global__ __launch_bounds__(256, 2) void h0_hmma(
    const __half* __restrict__ XA,
    const __half* __restrict__ WpHi,
    const __half* __restrict__ WpLo,
    const float* __restrict__ bp,
    __half* __restrict__ hout)
{
    const int tid = threadIdx.x;
    const int wid = tid >> 5, lane = tid & 31;
    const int bx = blockIdx.x;        // m tile: m0 = bx*32
    const int nb = blockIdx.y;        // n block of 128

    const __half* aP = XA + (bx * 2) * 4096 + lane * 8;
    const __half* bH = WpHi + ((nb * 16) * 8 + wid) * 256 + lane * 8;
    const __half* bL = WpLo + ((nb * 16) * 8 + wid) * 256 + lane * 8;

    float acc[2][2][4];
    #pragma unroll
    for (int a = 0; a < 2; a++)
        #pragma unroll
        for (int c = 0; c < 2; c++)
            #pragma unroll
            for (int d = 0; d < 4; d++) acc[a][c][d] = 0.0f;

    #pragma unroll
    for (int kt = 0; kt < 16; kt++) {
        const uint4 aq0 = *(const uint4*)(aP + kt * 256);
        const uint4 aq1 = *(const uint4*)(aP + 4096 + kt * 256);
        const uint4 qh  = *(const uint4*)(bH + kt * 2048);
        const uint4 ql  = *(const uint4*)(bL + kt * 2048);
        uint32_t af0[4] = {aq0.x, aq0.y, aq0.z, aq0.w};
        uint32_t af1[4] = {aq1.x, aq1.y, aq1.z, aq1.w};
        uint32_t bh[2][2], bl[2][2];
        bh[0][0] = qh.x; bh[0][1] = qh.y; bh[1][0] = qh.z; bh[1][1] = qh.w;
        bl[0][0] = ql.x; bl[0][1] = ql.y; bl[1][0] = ql.z; bl[1][1] = ql.w;
        #pragma unroll
        for (int f = 0; f < 2; f++) {
            mma16816(acc[0][f], af0, bh[f]);
            mma16816(acc[1][f], af1, bh[f]);
            mma16816(acc[0][f], af0, bl[f]);
            mma16816(acc[1][f], af1, bl[f]);
        }
    }

    const int lr = lane >> 2;
    const int lc = (lane & 3) * 2;
    const int ktj = nb * 8 + wid;
    #pragma unroll
    for (int mi = 0; mi < 2; mi++) {
        const int mt = bx * 2 + mi;
        __half* base = hout + (mt * 32 + ktj) * 256 + (lr * 4 + (lc >> 1)) * 8;
        #pragma unroll
        for (int f = 0; f < 2; f++) {
            const int n = nb * 128 + wid * 16 + f * 8 + lc;
            const float2 b2 = *(const float2*)(bp + n);
            const __half h00 = __float2half_rn(acc[mi][f][0] + b2.x);
            const __half h01 = __float2half_rn(acc[mi][f][1] + b2.y);
            const __half h10 = __float2half_rn(acc[mi][f][2] + b2.x);
            const __half h11 = __float2half_rn(acc[mi][f][3] + b2.y);
            uint2 w;
            w.x = (uint32_t)__half_as_ushort(h00) | ((uint32_t)__half_as_ushort(h01) << 16);
            w.y = (uint32_t)__half_as_ushort(h10) | ((uint32_t)__half_as_ushort(h11) << 16);
            *(uint2*)(base + 4 * f) = w;
        }
    }
}

// ============================================================================
// Merged step kernel — R15 champion ordering restored:
//   blocks [0,512)   : gates(t)
//   blocks [512,640) : logits(t-1)   (launched last; scheduler back-fills)
// Logits 'out' stores use st.global.cs (write-once data, evict-first in L2).
// ============================================================================
#define A_SMEM_BYTES 65536      // 64 rows x 512 k x 2B, fragment layout

__global__ __launch_bounds__(256, 2) void step_kernel(
    int t,
    const __half* __restrict__ hin,
    __half*       __restrict__ hout,
    const __half* __restrict__ WB,
    const float* __restrict__ xbT,
    const int* __restrict__ chars,
    float* __restrict__ cst,
    const __half* __restrict__ WoB,
    const float* __restrict__ bo,
    float* __restrict__ out)
{
    extern __shared__ __half sA[];
    const int tid = threadIdx.x;
    const int wid = tid >> 5, lane = tid & 31;
    const int bx = blockIdx.x;

    if (bx < 512) {
        // ======================= GATES PATH =======================
        const int bm = bx & 63, bnp = bx >> 6;      // 64 x 8
        const int m0 = bm * 64;
        const int bn0 = bnp * 2, bn1 = bn0 + 1;
        const int wm = wid >> 2, wn = wid & 3;      // 2m x 4n warps
        const int lr = lane >> 2;
        const int lc = (lane & 3) * 2;

        // Stage full A tile to smem (fragment-contiguous range).
        {
            const uint32_t sbase = smem_u32(sA);
            const __half* aG = hin + (bm * 4 * 32) * 256;
            #pragma unroll
            for (int i = 0; i < 16; i++) {
                const int ch = tid + i * 256;          // 0..4095 16B-chunks
                cp_async16(sbase + ch * 16, aG + ch * 8);
            }
            CP_COMMIT();
        }

        // Hoisted: char indices for epilogue (overlaps with GEMM).
        int cidx[2][2];
        #pragma unroll
        for (int mi = 0; mi < 2; mi++)
            #pragma unroll
            for (int rh = 0; rh < 2; rh++) {
                const int m = m0 + wm*32 + mi*16 + lr + rh*8;
                int idx = 0;
                if (t > 0) {
                    int cc = chars[m * CD + (t - 1)];
                    idx = (cc >= 0 && cc < AD) ? cc : 0;
                }
                cidx[mi][rh] = idx;
            }

        // B fragment bases for the two bn blocks (kt stride 2048)
        const __half* bP0 = WB + (bn0 * 256 + wn * 2) * 256 + lane * 8;
        const __half* bP1 = WB + (bn1 * 256 + wn * 2) * 256 + lane * 8;

        // Prefetch B stage 0 while A streams in
        uint4 Ba[2][2], Bb[2][2];
        Ba[0][0] = *(const uint4*)(bP0);
        Ba[1][0] = *(const uint4*)(bP0 + 256);
        Bb[0][0] = *(const uint4*)(bP1);
        Bb[1][0] = *(const uint4*)(bP1 + 256);

        float acc[2][2][4][4];   // [mi][blk][f][k]
        #pragma unroll
        for (int a = 0; a < 2; a++)
            #pragma unroll
            for (int b = 0; b < 2; b++)
                #pragma unroll
                for (int c = 0; c < 4; c++)
                    #pragma unroll
                    for (int d = 0; d < 4; d++) acc[a][b][c][d] = 0.0f;

        CP_WAIT0();
        __syncthreads();

        const __half* aS0 = sA + (wm * 2) * 8192 + lane * 8;       // mi=0
        const __half* aS1 = aS0 + 8192;                            // mi=1

        #pragma unroll
        for (int kt = 0; kt < 32; kt++) {
            const int cur = kt & 1, nxt = cur ^ 1;
            if (kt < 31) {
                const int kb = (kt + 1) * 2048;
                Ba[0][nxt] = *(const uint4*)(bP0 + kb);
                Ba[1][nxt] = *(const uint4*)(bP0 + kb + 256);
                Bb[0][nxt] = *(const uint4*)(bP1 + kb);
                Bb[1][nxt] = *(const uint4*)(bP1 + kb + 256);
            }
            const uint4 aq0 = *(const uint4*)(aS0 + kt * 256);     // LDS.128
            const uint4 aq1 = *(const uint4*)(aS1 + kt * 256);
            uint32_t af0[4] = {aq0.x, aq0.y, aq0.z, aq0.w};
            uint32_t af1[4] = {aq1.x, aq1.y, aq1.z, aq1.w};
            uint32_t bf0[4][2], bf1[4][2];
            bf0[0][0] = Ba[0][cur].x; bf0[0][1] = Ba[0][cur].y;
            bf0[1][0] = Ba[0][cur].z; bf0[1][1] = Ba[0][cur].w;
            bf0[2][0] = Ba[1][cur].x; bf0[2][1] = Ba[1][cur].y;
            bf0[3][0] = Ba[1][cur].z; bf0[3][1] = Ba[1][cur].w;
            bf1[0][0] = Bb[0][cur].x; bf1[0][1] = Bb[0][cur].y;
            bf1[1][0] = Bb[0][cur].z; bf1[1][1] = Bb[0][cur].w;
            bf1[2][0] = Bb[1][cur].x; bf1[2][1] = Bb[1][cur].y;
            bf1[3][0] = Bb[1][cur].z; bf1[3][1] = Bb[1][cur].w;
            #pragma unroll
            for (int f = 0; f < 4; f++) {
                mma16816(acc[0][0][f], af0, bf0[f]);
                mma16816(acc[1][0][f], af1, bf0[f]);
                mma16816(acc[0][1][f], af0, bf1[f]);
                mma16816(acc[1][1][f], af1, bf1[f]);
            }
        }

        // Epilogue: per bn block, gates -> LSTM cell update.
        #pragma unroll
        for (int blk = 0; blk < 2; blk++) {
            const int bn = bn0 + blk;
            float* cp_base = cst + (((bm * 16 + bn) * 8 + wid) * 256 + lane * 8);
            #pragma unroll
            for (int mi = 0; mi < 2; mi++) {
                float4 cold = (t > 0) ? *(float4*)(cp_base + mi * 4)
                                      : make_float4(0.f, 0.f, 0.f, 0.f);
                float cn_[4];
                uint32_t ph[2];
                #pragma unroll
                for (int rh = 0; rh < 2; rh++) {
                    const float* xb = xbT + ((cidx[mi][rh] * 16 + bn) * 4 + wn) * 32 + lc * 4;
                    const float4 x0 = *(const float4*)xb;
                    const float4 x1 = *(const float4*)(xb + 4);
                    __half hv[2];
                    #pragma unroll
                    for (int cpp = 0; cpp < 2; cpp++) {
                        const float4 xv = cpp ? x1 : x0;
                        const int k = rh * 2 + cpp;
                        const float gi = acc[mi][blk][0][k] + xv.x;
                        const float gf = acc[mi][blk][1][k] + xv.y;
                        const float gg = acc[mi][blk][2][k] + xv.z;
                        const float go = acc[mi][blk][3][k] + xv.w;
                        const float co = (k == 0) ? cold.x : (k == 1) ? cold.y
                                       : (k == 2) ? cold.z : cold.w;
                        const float cn = sigmoidf_(gf) * co + sigmoidf_(gi) * tanhf_(gg);
                        cn_[k] = cn;
                        hv[cpp] = __float2half_rn(sigmoidf_(go) * tanhf_(cn));
                    }
                    ph[rh] = (uint32_t)__half_as_ushort(hv[0])
                           | ((uint32_t)__half_as_ushort(hv[1]) << 16);
                }
                const int mt = bm*4 + wm*2 + mi;
                const int ktj = bn*2 + (wn >> 1);
                uint2 w; w.x = ph[0]; w.y = ph[1];
                *(uint2*)(hout + (mt*32 + ktj)*256 + lane*8 + (wn & 1)*4) = w;
                *(float4*)(cp_base + mi * 4) = make_float4(cn_[0], cn_[1], cn_[2], cn_[3]);
            }
        }
    } else {
        // ======================= LOGITS PATH (for step t-1) =======================
        if (t == 0) return;
        const int m0 = (bx - 512) * 32;
        const int tprev = t - 1;

        const __half* aP = hin + ((m0 >> 4) * 32) * 256 + lane * 8;
        const __half* bP = WoB + (wid * 32 + lane) * 8;

        float acc[2][2][4];
        #pragma unroll
        for (int a = 0; a < 2; a++)
            #pragma unroll
            for (int b = 0; b < 2; b++)
                #pragma unroll
                for (int c = 0; c < 4; c++) acc[a][b][c] = 0.0f;

        #pragma unroll
        for (int kt = 0; kt < 32; kt++) {
            const uint4 aq0 = *(const uint4*)(aP + kt * 256);
            const uint4 aq1 = *(const uint4*)(aP + 8192 + kt * 256);
            const uint4 bq  = *(const uint4*)(bP + kt * 2048);
            uint32_t af0[4] = {aq0.x, aq0.y, aq0.z, aq0.w};
            uint32_t af1[4] = {aq1.x, aq1.y, aq1.z, aq1.w};
            uint32_t bf[2][2];
            bf[0][0] = bq.x; bf[0][1] = bq.y;
            bf[1][0] = bq.z; bf[1][1] = bq.w;
            mma16816(acc[0][0], af0, bf[0]);
            mma16816(acc[0][1], af0, bf[1]);
            mma16816(acc[1][0], af1, bf[0]);
            mma16816(acc[1][1], af1, bf[1]);
        }

        const int lr = lane >> 2;
        const int lc = (lane & 3) * 2;
        #pragma unroll
        for (int mi = 0; mi < 2; mi++) {
            #pragma unroll
            for (int rh = 0; rh < 2; rh++) {
                const int m = m0 + mi*16 + lr + rh*8;
                float* orow = out + m * (CD * AD) + tprev * AD;
                #pragma unroll
                for (int f = 0; f < 2; f++) {
                    const int n = wid*16 + f*8 + lc;
                    const float2 b2 = *(const float2*)(bo + n);
                    float2 v;
                    v.x = acc[mi][f][rh*2 + 0] + b2.x;
                    v.y = acc[mi][f][rh*2 + 1] + b2.y;
                    stg_cs_f2(orow + n, v);
                }
            }
        }
    }
}

// ============================================================================
// Standalone logits (final step).
// ============================================================================
__global__ __launch_bounds__(256, 2) void logits_kernel(
    const __half* __restrict__ h,
    const __half* __restrict__ WoB,
    const float* __restrict__ bo,
    float* __restrict__ out, int t)
{
    const int tid = threadIdx.x;
    const int wid = tid >> 5, lane = tid & 31;
    const int m0 = blockIdx.x * 32;

    const __half* aP = h + ((m0 >> 4) * 32) * 256 + lane * 8;
    const __half* bP = WoB + (wid * 32 + lane) * 8;

    float acc[2][2][4];
    #pragma unroll
    for (int a = 0; a < 2; a++)
        #pragma unroll
        for (int b = 0; b < 2; b++)
            #pragma unroll
            for (int c = 0; c < 4; c++) acc[a][b][c] = 0.0f;

    #pragma unroll
    for (int kt = 0; kt < 32; kt++) {
        const uint4 aq0 = *(const uint4*)(aP + kt * 256);
        const uint4 aq1 = *(const uint4*)(aP + 8192 + kt * 256);
        const uint4 bq  = *(const uint4*)(bP + kt * 2048);
        uint32_t af0[4] = {aq0.x, aq0.y, aq0.z, aq0.w};
        uint32_t af1[4] = {aq1.x, aq1.y, aq1.z, aq1.w};
        uint32_t bf[2][2];
        bf[0][0] = bq.x; bf[0][1] = bq.y;
        bf[1][0] = bq.z; bf[1][1] = bq.w;
        mma16816(acc[0][0], af0, bf[0]);
        mma16816(acc[0][1], af0, bf[1]);
        mma16816(acc[1][0], af1, bf[0]);
        mma16816(acc[1][1], af1, bf[1]);
    }

    const int lr = lane >> 2;
    const int lc = (lane & 3) * 2;
    #pragma unroll
    for (int mi = 0; mi < 2; mi++) {
        #pragma unroll
        for (int rh = 0; rh < 2; rh++) {
            const int m = m0 + mi*16 + lr + rh*8;
            float* orow = out + m * (CD * AD) + t * AD;
            #pragma unroll
            for (int f = 0; f < 2; f++) {
                const int n = wid*16 + f*8 + lc;
                const float2 b2 = *(const float2*)(bo + n);
                float2 v;
                v.x = acc[mi][f][rh*2 + 0] + b2.x;
                v.y = acc[mi][f][rh*2 + 1] + b2.y;
                stg_cs_f2(orow + n, v);
            }
        }
    }
}

// ============================================================================
// kernel_launch
// ============================================================================
extern "C" void kernel_launch(void* const* d_in, const int* in_sizes, int n_in,
                              void* d_out, int out_size)
{
    const float* X    = (const float*)d_in[0];
    const int*   tc   = (const int*)  d_in[1];
    const float* Wp   = (const float*)d_in[2];
    const float* bp   = (const float*)d_in[3];
    const float* Wih  = (const float*)d_in[4];
    const float* Whh  = (const float*)d_in[5];
    const float* bih  = (const float*)d_in[6];
    const float* bhh  = (const float*)d_in[7];
    const float* Wo   = (const float*)d_in[8];
    const float* bo   = (const float*)d_in[9];
    float* out = (float*)d_out;

    __half *h0b, *h1b, *wb, *wob, *xa, *wphi, *wplo;
    float *cS, *xb;
    cudaGetSymbolAddress((void**)&h0b,  g_h0);
    cudaGetSymbolAddress((void**)&h1b,  g_h1);
    cudaGetSymbolAddress((void**)&cS,   g_c);
    cudaGetSymbolAddress((void**)&wb,   g_WB);
    cudaGetSymbolAddress((void**)&wob,  g_WoB);
    cudaGetSymbolAddress((void**)&xb,   g_xbT);
    cudaGetSymbolAddress((void**)&xa,   g_XA);
    cudaGetSymbolAddress((void**)&wphi, g_WpHi);
    cudaGetSymbolAddress((void**)&wplo, g_WpLo);

    cudaFuncSetAttribute(step_kernel, cudaFuncAttributeMaxDynamicSharedMemorySize,
                         A_SMEM_BYTES);

    prep_all<<<9984, 256>>>(Whh, X, Wih, bih, bhh, Wo, Wp,
                            wb, xa, xb, wob, wphi, wplo);
    h0_hmma<<<dim3(128, 4), 256>>>(xa, wphi, wplo, bp, h0b);

    for (int t = 0; t < CD; t++) {
        const __half* hin  = (t & 1) ? h1b : h0b;
        __half*       hout = (t & 1) ? h0b : h1b;
        const int nblk = (t == 0) ? 512 : 640;     // gates + (t>0) logits(t-1)
        step_kernel<<<nblk, 256, A_SMEM_BYTES>>>(
            t, hin, hout, wb, xb, tc, cS, wob, bo, out);
    }
    // final logits for t = 15
    logits_kernel<<<BWN / 32, 256>>>(
        (CD & 1) ? h1b : h0b, wob, bo, out, CD - 1);
}